// round 1
// baseline (speedup 1.0000x reference)
#include <cuda_runtime.h>
#include <math.h>

// ---- problem constants ----
#define A_DIM 56
#define E_DIM 128
#define LAMBDA_INIT 0.7f
#define LN_EPS 1e-5f
#define SCALING 0.25f   // HD^-0.5, HD=16

// ---- smem layout (in floats) ----
#define SX_STRIDE 134              // 3 + 128 + 3
#define SZ_SX     (56 * 134)       // 7504
#define SH1_STRIDE 62              // 3 + 56 + 3
#define SZ_SH1    (128 * 62)       // 7936
#define SZ_SK     (56 * 128)       // 7168
#define SZ_SW     3584             // staging buffer (max of all chunk sizes)

#define OFF_SX   0
#define OFF_SH1  (OFF_SX + SZ_SX)
#define OFF_SK   (OFF_SH1 + SZ_SH1)
#define OFF_SW   (OFF_SK + SZ_SK)
#define OFF_Q    (OFF_SW + SZ_SW)
#define OFF_QN   (OFF_Q + 128)
#define OFF_SA   (OFF_QN + 128)    // 8 rows, stride 60
#define OFF_SA2  (OFF_SA + 8 * 60) // 4 rows, stride 60
#define OFF_SC   (OFF_SA2 + 4 * 60)
#define SMEM_FLOATS (OFF_SC + 8)

__device__ __forceinline__ float silu_f(float v) {
    return v / (1.0f + __expf(-v));
}

extern __shared__ float sm[];

__global__ void __launch_bounds__(256)
atlas_mdattn_kernel(
    const float* __restrict__ x,       // [B,56,128]
    const float* __restrict__ w_emb,   // [56,56,7]
    const float* __restrict__ b_emb,   // [56]
    const float* __restrict__ w_atlas, // [128,128,7]
    const float* __restrict__ b_atlas, // [128]
    const float* __restrict__ w_k,     // [128,128]
    const float* __restrict__ qn_w, const float* __restrict__ qn_b,
    const float* __restrict__ kn_w, const float* __restrict__ kn_b,
    const float* __restrict__ lq1, const float* __restrict__ lk1,
    const float* __restrict__ lq2, const float* __restrict__ lk2,
    float* __restrict__ out)           // [B,56]
{
    const int b = blockIdx.x;
    const int t = threadIdx.x;

    float* SX  = sm + OFF_SX;   // padded x:  SX[l][3+e]
    float* SH1 = sm + OFF_SH1;  // padded h1ᵀ: SH1[e][3+a]
    float* SK  = sm + OFF_SK;   // k / normalized k: SK[l][o]
    float* SW  = sm + OFF_SW;   // weight staging
    float* Sq  = sm + OFF_Q;    // q accumulation (sum over a)
    float* Sqn = sm + OFF_QN;   // normalized+scaled q
    float* SA  = sm + OFF_SA;   // attn logits / probs, 8 x 60
    float* SA2 = sm + OFF_SA2;  // diff softmax, 4 x 60
    float* Ssc = sm + OFF_SC;   // scalars: [0] = lambda_full

    // ---------- init ----------
    for (int i = t; i < SZ_SX; i += 256)  SX[i]  = 0.0f;
    for (int i = t; i < SZ_SH1; i += 256) SH1[i] = 0.0f;
    if (t < 128) Sq[t] = 0.0f;
    if (t == 0) {
        float s1 = 0.f, s2 = 0.f;
        #pragma unroll
        for (int d = 0; d < 16; ++d) { s1 += lq1[d] * lk1[d]; s2 += lq2[d] * lk2[d]; }
        Ssc[0] = __expf(s1) - __expf(s2) + LAMBDA_INIT;
    }
    __syncthreads();

    // load x into padded SX
    const float* xb = x + (size_t)b * (A_DIM * E_DIM);
    for (int i = t; i < A_DIM * E_DIM; i += 256) {
        int l = i >> 7, e = i & 127;
        SX[l * SX_STRIDE + 3 + e] = xb[i];
    }
    __syncthreads();

    // ---------- phase 1: conv1 (atlas-channel conv over e) + SiLU ----------
    // h1[oa][e] = silu( sum_{ia,dk} w_emb[oa][ia][dk] * x[ia][e+dk-3] )
    {
        const int eo = t & 31, ot = t >> 5;          // 32 e-tiles x 8 oa-tiles
        const int e_base = eo * 4, oa_base = ot * 7; // 4 e x 7 oa per thread
        float acc[7][4];
        #pragma unroll
        for (int i = 0; i < 7; ++i)
            #pragma unroll
            for (int j = 0; j < 4; ++j) acc[i][j] = 0.0f;

        #pragma unroll 1
        for (int ia0 = 0; ia0 < 56; ia0 += 8) {
            __syncthreads();
            // stage w_emb chunk: SW[(ic*7+dk)*56 + oa]
            for (int i = t; i < 8 * 7 * 56; i += 256) {
                int oa = i / 56, r = i % 56;  // r = ic*7+dk
                SW[r * 56 + oa] = w_emb[oa * 392 + ia0 * 7 + r];
            }
            __syncthreads();
            #pragma unroll 1
            for (int ic = 0; ic < 8; ++ic) {
                const int ia = ia0 + ic;
                float xv[10];
                #pragma unroll
                for (int c = 0; c < 10; ++c)
                    xv[c] = SX[ia * SX_STRIDE + e_base + c];
                #pragma unroll
                for (int dk = 0; dk < 7; ++dk) {
                    #pragma unroll
                    for (int i = 0; i < 7; ++i) {
                        float wv = SW[(ic * 7 + dk) * 56 + oa_base + i];
                        #pragma unroll
                        for (int j = 0; j < 4; ++j)
                            acc[i][j] += wv * xv[dk + j];
                    }
                }
            }
        }
        // SiLU + store transposed into padded SH1: SH1[e][3+oa]
        #pragma unroll
        for (int i = 0; i < 7; ++i) {
            float bias = b_emb[oa_base + i];
            #pragma unroll
            for (int j = 0; j < 4; ++j) {
                float v = silu_f(acc[i][j] + bias);
                SH1[(e_base + j) * SH1_STRIDE + 3 + oa_base + i] = v;
            }
        }
    }
    __syncthreads();

    // ---------- phase 2: conv2 (embed-channel conv over a) + SiLU + mean-pool -> q ----------
    // h2[oe][a] = silu( sum_{ie,dk} w_atlas[oe][ie][dk] * h1T[ie][a+dk-3] ); q[oe] = mean_a h2
    {
        const int at = t & 7, ot = t >> 3;            // 8 a-tiles x 32 oe-tiles
        const int a_base = at * 7, oe_base = ot * 4;  // 7 a x 4 oe per thread
        float acc[7][4];
        #pragma unroll
        for (int j = 0; j < 7; ++j)
            #pragma unroll
            for (int i = 0; i < 4; ++i) acc[j][i] = 0.0f;

        #pragma unroll 1
        for (int ie0 = 0; ie0 < 128; ie0 += 4) {
            __syncthreads();
            // stage w_atlas chunk: SW[(ic*7+dk)*128 + oe]
            for (int i = t; i < 4 * 7 * 128; i += 256) {
                int oe = i / 28, r = i % 28; // r = ic*7+dk
                SW[r * 128 + oe] = w_atlas[oe * 896 + ie0 * 7 + r];
            }
            __syncthreads();
            #pragma unroll 1
            for (int ic = 0; ic < 4; ++ic) {
                const int ie = ie0 + ic;
                float hv[13];
                #pragma unroll
                for (int c = 0; c < 13; ++c)
                    hv[c] = SH1[ie * SH1_STRIDE + a_base + c];
                #pragma unroll
                for (int dk = 0; dk < 7; ++dk) {
                    #pragma unroll
                    for (int i = 0; i < 4; ++i) {
                        float wv = SW[(ic * 7 + dk) * 128 + oe_base + i];
                        #pragma unroll
                        for (int j = 0; j < 7; ++j)
                            acc[j][i] += wv * hv[dk + j];
                    }
                }
            }
        }
        // SiLU + bias + partial sum over a -> Sq
        #pragma unroll
        for (int i = 0; i < 4; ++i) {
            float bias = b_atlas[oe_base + i];
            float s = 0.0f;
            #pragma unroll
            for (int j = 0; j < 7; ++j)
                s += silu_f(acc[j][i] + bias);
            atomicAdd(&Sq[oe_base + i], s);
        }
    }
    __syncthreads();

    // ---------- phase 3: k projection  k[l][o] = sum_e x[l][e] * w_k[o][e] ----------
    {
        const int lt = t & 7, ot = t >> 3;
        const int l_base = lt * 7, o_base = ot * 4;
        float acc[7][4];
        #pragma unroll
        for (int j = 0; j < 7; ++j)
            #pragma unroll
            for (int i = 0; i < 4; ++i) acc[j][i] = 0.0f;

        #pragma unroll 1
        for (int e0 = 0; e0 < 128; e0 += 16) {
            __syncthreads();
            // stage w_k chunk transposed: SW[el*128 + o]
            for (int i = t; i < 2048; i += 256) {
                int o = i >> 4, el = i & 15;
                SW[el * 128 + o] = w_k[o * 128 + e0 + el];
            }
            __syncthreads();
            #pragma unroll 1
            for (int el = 0; el < 16; ++el) {
                float xv[7];
                #pragma unroll
                for (int j = 0; j < 7; ++j)
                    xv[j] = SX[(l_base + j) * SX_STRIDE + 3 + e0 + el];
                #pragma unroll
                for (int i = 0; i < 4; ++i) {
                    float wv = SW[el * 128 + o_base + i];
                    #pragma unroll
                    for (int j = 0; j < 7; ++j)
                        acc[j][i] += wv * xv[j];
                }
            }
        }
        #pragma unroll
        for (int j = 0; j < 7; ++j)
            #pragma unroll
            for (int i = 0; i < 4; ++i)
                SK[(l_base + j) * 128 + o_base + i] = acc[j][i];
    }
    __syncthreads();

    // ---------- phase 4: layernorms ----------
    // q layernorm (8 groups of 16) + scaling
    if (t < 8) {
        const int h = t;
        float qv[16];
        float m = 0.0f;
        #pragma unroll
        for (int d = 0; d < 16; ++d) { qv[d] = Sq[h * 16 + d] * (1.0f / 56.0f); m += qv[d]; }
        m *= (1.0f / 16.0f);
        float var = 0.0f;
        #pragma unroll
        for (int d = 0; d < 16; ++d) { float dd = qv[d] - m; var += dd * dd; }
        var *= (1.0f / 16.0f);
        float rs = rsqrtf(var + LN_EPS);
        #pragma unroll
        for (int d = 0; d < 16; ++d)
            Sqn[h * 16 + d] = ((qv[d] - m) * rs * qn_w[d] + qn_b[d]) * SCALING;
    }
    // k layernorm in place (56*8 = 448 groups of 16)
    for (int g = t; g < 448; g += 256) {
        const int l = g >> 3, h = g & 7;
        float* kp = SK + l * 128 + h * 16;
        float m = 0.0f;
        #pragma unroll
        for (int d = 0; d < 16; ++d) m += kp[d];
        m *= (1.0f / 16.0f);
        float var = 0.0f;
        #pragma unroll
        for (int d = 0; d < 16; ++d) { float dd = kp[d] - m; var += dd * dd; }
        var *= (1.0f / 16.0f);
        float rs = rsqrtf(var + LN_EPS);
        #pragma unroll
        for (int d = 0; d < 16; ++d)
            kp[d] = (kp[d] - m) * rs * kn_w[d] + kn_b[d];
    }
    __syncthreads();

    // ---------- phase 5: attention logits + softmax over l ----------
    for (int id = t; id < 448; id += 256) {
        const int l = id >> 3, h = id & 7;
        const float* qp = Sqn + h * 16;
        const float* kp = SK + l * 128 + h * 16;
        float s = 0.0f;
        #pragma unroll
        for (int d = 0; d < 16; ++d) s += qp[d] * kp[d];
        SA[h * 60 + l] = s;
    }
    __syncthreads();
    if (t < 8) {
        float* row = SA + t * 60;
        float mx = -1e30f;
        for (int l = 0; l < 56; ++l) mx = fmaxf(mx, row[l]);
        float sum = 0.0f;
        for (int l = 0; l < 56; ++l) { float e = __expf(row[l] - mx); row[l] = e; sum += e; }
        float inv = 1.0f / sum;
        for (int l = 0; l < 56; ++l) row[l] *= inv;
    }
    __syncthreads();

    // ---------- phase 6: differential combine + second softmax + head mean ----------
    if (t < 4) {
        const float lam = Ssc[0];
        const float* r0 = SA + (2 * t) * 60;
        const float* r1 = SA + (2 * t + 1) * 60;
        float* dst = SA2 + t * 60;
        float mx = -1e30f;
        for (int l = 0; l < 56; ++l) {
            float v = r0[l] - lam * r1[l];
            dst[l] = v;
            mx = fmaxf(mx, v);
        }
        float sum = 0.0f;
        for (int l = 0; l < 56; ++l) { float e = __expf(dst[l] - mx); dst[l] = e; sum += e; }
        float inv = 1.0f / sum;
        for (int l = 0; l < 56; ++l) dst[l] *= inv;
    }
    __syncthreads();
    if (t < 56) {
        out[(size_t)b * 56 + t] =
            0.25f * (SA2[t] + SA2[60 + t] + SA2[120 + t] + SA2[180 + t]);
    }
}

extern "C" void kernel_launch(void* const* d_in, const int* in_sizes, int n_in,
                              void* d_out, int out_size) {
    const float* x       = (const float*)d_in[0];
    const float* w_emb   = (const float*)d_in[1];
    const float* b_emb   = (const float*)d_in[2];
    const float* w_atlas = (const float*)d_in[3];
    const float* b_atlas = (const float*)d_in[4];
    const float* w_k     = (const float*)d_in[5];
    const float* qn_w    = (const float*)d_in[6];
    const float* qn_b    = (const float*)d_in[7];
    const float* kn_w    = (const float*)d_in[8];
    const float* kn_b    = (const float*)d_in[9];
    const float* lq1     = (const float*)d_in[10];
    const float* lk1     = (const float*)d_in[11];
    const float* lq2     = (const float*)d_in[12];
    const float* lk2     = (const float*)d_in[13];
    float* out = (float*)d_out;

    const int B = in_sizes[0] / (A_DIM * E_DIM);
    const size_t smem = SMEM_FLOATS * sizeof(float);
    cudaFuncSetAttribute(atlas_mdattn_kernel,
                         cudaFuncAttributeMaxDynamicSharedMemorySize, (int)smem);
    atlas_mdattn_kernel<<<B, 256, smem>>>(
        x, w_emb, b_emb, w_atlas, b_atlas, w_k,
        qn_w, qn_b, kn_w, kn_b, lq1, lk1, lq2, lk2, out);
}

// round 2
// speedup vs baseline: 2.6781x; 2.6781x over previous
#include <cuda_runtime.h>
#include <math.h>

// ---- problem constants ----
#define A_DIM 56
#define E_DIM 128
#define LAMBDA_INIT 0.7f
#define LN_EPS 1e-5f
#define SCALING 0.25f   // HD^-0.5, HD=16

// ---- smem layout (32-bit words) ----
// SX : [2][64][134]  tf32 x, padded (3 halo left, 3 right, rows 56..63 zero)
#define SX_BSTRIDE (64 * 134)      // 8576
#define SZ_SX      (2 * SX_BSTRIDE)
// SH1: [2][128][72]  tf32 h1^T (col = a+3, halo zero);  reused later as SK fp32 [2][64][132]
#define SH1_BSTRIDE (128 * 72)     // 9216
#define SZ_SH1      (2 * SH1_BSTRIDE)
#define SK_BSTRIDE  (64 * 132)     // 8448 (fits in SH1 region)

#define OFF_SX   0
#define OFF_SH1  (OFF_SX + SZ_SX)                 // 17152
#define OFF_SQ   (OFF_SH1 + SZ_SH1)               // 35584
#define OFF_SQN  (OFF_SQ + 256)
#define OFF_SA   (OFF_SQN + 256)                  // [2][8][60]
#define OFF_SA2  (OFF_SA + 960)                   // [2][4][60]
#define OFF_SC   (OFF_SA2 + 480)
#define SMEM_WORDS (OFF_SC + 4)

__device__ __forceinline__ unsigned f2tf(float f) {
    unsigned u;
    asm("cvt.rna.tf32.f32 %0, %1;" : "=r"(u) : "f"(f));
    return u;
}
__device__ __forceinline__ float silu_f(float v) {
    return v / (1.0f + __expf(-v));
}
__device__ __forceinline__ void mma_tf32(float* d, const unsigned* a, const unsigned* b) {
    asm volatile(
        "mma.sync.aligned.m16n8k8.row.col.f32.tf32.tf32.f32 "
        "{%0,%1,%2,%3}, {%4,%5,%6,%7}, {%8,%9}, {%0,%1,%2,%3};"
        : "+f"(d[0]), "+f"(d[1]), "+f"(d[2]), "+f"(d[3])
        : "r"(a[0]), "r"(a[1]), "r"(a[2]), "r"(a[3]), "r"(b[0]), "r"(b[1]));
}

extern __shared__ unsigned smw[];

__global__ void __launch_bounds__(256, 1)
atlas_mdattn_tc(
    const float* __restrict__ x,       // [B,56,128]
    const float* __restrict__ w_emb,   // [56,56,7]  (56 x 392)
    const float* __restrict__ b_emb,   // [56]
    const float* __restrict__ w_atlas, // [128,128,7] (128 x 896)
    const float* __restrict__ b_atlas, // [128]
    const float* __restrict__ w_k,     // [128,128]
    const float* __restrict__ qn_w, const float* __restrict__ qn_b,
    const float* __restrict__ kn_w, const float* __restrict__ kn_b,
    const float* __restrict__ lq1, const float* __restrict__ lk1,
    const float* __restrict__ lq2, const float* __restrict__ lk2,
    float* __restrict__ out)           // [B,56]
{
    const int t = threadIdx.x;
    const int lane = t & 31, wid = t >> 5;
    const int g = lane >> 2, tg = lane & 3;   // m16n8k8 fragment coords

    unsigned* SX  = smw + OFF_SX;
    unsigned* SH1 = smw + OFF_SH1;
    float* Sq  = (float*)(smw + OFF_SQ);   // [2][128] mean-pool sums
    float* Sqn = (float*)(smw + OFF_SQN);  // [2][128] normalized q
    float* SA  = (float*)(smw + OFF_SA);   // [2][8][60]
    float* SA2 = (float*)(smw + OFF_SA2);  // [2][4][60]
    float* Ssc = (float*)(smw + OFF_SC);
    float* SK  = (float*)SH1;              // [2][64][132] after conv2 done

    // ---------------- init ----------------
    {
        uint4 z = make_uint4(0, 0, 0, 0);
        uint4* p = (uint4*)smw;
        for (int i = t; i < (SZ_SX + SZ_SH1) / 4; i += 256) p[i] = z;
    }
    if (t == 0) {
        float s1 = 0.f, s2 = 0.f;
        #pragma unroll
        for (int d = 0; d < 16; ++d) { s1 += lq1[d] * lk1[d]; s2 += lq2[d] * lk2[d]; }
        Ssc[0] = __expf(s1) - __expf(s2) + LAMBDA_INIT;
    }
    __syncthreads();

    // load x (2 batches), convert to tf32 bits, halo-padded
    const float* xb = x + (size_t)blockIdx.x * 2 * (A_DIM * E_DIM);
    #pragma unroll
    for (int bb = 0; bb < 2; ++bb) {
        for (int i = t; i < A_DIM * E_DIM; i += 256) {
            int l = i >> 7, e = i & 127;
            SX[bb * SX_BSTRIDE + l * 134 + 3 + e] = f2tf(xb[bb * A_DIM * E_DIM + i]);
        }
    }
    __syncthreads();

    // ================ conv1: D[oa 64, (b,e) 256] = Wemb[64,392] x im2col(x) ================
    {
        const int mg = wid & 1, ng = wid >> 1;         // 2 m-groups x 4 n-groups
        const int mbase = mg * 32;
        const int batch = ng >> 1;
        const int ebase = (ng * 64) & 127;
        const unsigned* SXb = SX + batch * SX_BSTRIDE;

        float d[2][8][4];
        #pragma unroll
        for (int mi = 0; mi < 2; ++mi)
            #pragma unroll
            for (int ni = 0; ni < 8; ++ni)
                #pragma unroll
                for (int r = 0; r < 4; ++r) d[mi][ni][r] = 0.f;

        const int r0a = mbase + g,      r1a = mbase + g + 8;    // mi=0 rows
        const int r0b = mbase + 16 + g, r1b = mbase + 24 + g;   // mi=1 rows
        float af[2][4];
        // prefetch ks=0
        {
            const float* p = w_emb + tg;
            af[0][0] = (r0a < 56) ? p[r0a * 392]     : 0.f;
            af[0][1] = (r1a < 56) ? p[r1a * 392]     : 0.f;
            af[0][2] = (r0a < 56) ? p[r0a * 392 + 4] : 0.f;
            af[0][3] = (r1a < 56) ? p[r1a * 392 + 4] : 0.f;
            af[1][0] = (r0b < 56) ? p[r0b * 392]     : 0.f;
            af[1][1] = (r1b < 56) ? p[r1b * 392]     : 0.f;
            af[1][2] = (r0b < 56) ? p[r0b * 392 + 4] : 0.f;
            af[1][3] = (r1b < 56) ? p[r1b * 392 + 4] : 0.f;
        }
        #pragma unroll 1
        for (int ks = 0; ks < 49; ++ks) {
            unsigned a[2][4];
            #pragma unroll
            for (int mi = 0; mi < 2; ++mi)
                #pragma unroll
                for (int r = 0; r < 4; ++r) a[mi][r] = f2tf(af[mi][r]);
            // prefetch next A
            if (ks < 48) {
                const float* p = w_emb + (ks + 1) * 8 + tg;
                af[0][0] = (r0a < 56) ? p[r0a * 392]     : 0.f;
                af[0][1] = (r1a < 56) ? p[r1a * 392]     : 0.f;
                af[0][2] = (r0a < 56) ? p[r0a * 392 + 4] : 0.f;
                af[0][3] = (r1a < 56) ? p[r1a * 392 + 4] : 0.f;
                af[1][0] = (r0b < 56) ? p[r0b * 392]     : 0.f;
                af[1][1] = (r1b < 56) ? p[r1b * 392]     : 0.f;
                af[1][2] = (r0b < 56) ? p[r0b * 392 + 4] : 0.f;
                af[1][3] = (r1b < 56) ? p[r1b * 392 + 4] : 0.f;
            }
            const int k0 = ks * 8 + tg, k1 = k0 + 4;
            const int ia0 = k0 / 7, dk0 = k0 % 7;
            const int ia1 = k1 / 7, dk1 = k1 % 7;
            const unsigned* B0 = SXb + ia0 * 134 + ebase + g + dk0;  // x[ia0][e+dk0-3]
            const unsigned* B1 = SXb + ia1 * 134 + ebase + g + dk1;
            #pragma unroll
            for (int ni = 0; ni < 8; ++ni) {
                unsigned b[2] = { B0[ni * 8], B1[ni * 8] };
                mma_tf32(d[0][ni], a[0], b);
                mma_tf32(d[1][ni], a[1], b);
            }
        }
        // epilogue: + bias, SiLU, store transposed as tf32 into SH1[batch][e][oa+3]
        #pragma unroll
        for (int mi = 0; mi < 2; ++mi)
            #pragma unroll
            for (int r2 = 0; r2 < 2; ++r2) {
                int oa = mbase + mi * 16 + g + r2 * 8;
                if (oa < 56) {
                    float bias = b_emb[oa];
                    #pragma unroll
                    for (int ni = 0; ni < 8; ++ni)
                        #pragma unroll
                        for (int c = 0; c < 2; ++c) {
                            int e = ebase + ni * 8 + tg * 2 + c;
                            float v = silu_f(d[mi][ni][r2 * 2 + c] + bias);
                            SH1[batch * SH1_BSTRIDE + e * 72 + oa + 3] = f2tf(v);
                        }
                }
            }
    }
    __syncthreads();

    // ================ conv2: D[oe 128, (b,a) 128] = Watlas[128,896] x im2col(h1T) ========
    {
        const int mg = wid & 3, batch = wid >> 2;      // 4 m-groups x 2 batches
        const int mbase = mg * 32;
        const unsigned* SHb = SH1 + batch * SH1_BSTRIDE;

        float d[2][8][4];
        #pragma unroll
        for (int mi = 0; mi < 2; ++mi)
            #pragma unroll
            for (int ni = 0; ni < 8; ++ni)
                #pragma unroll
                for (int r = 0; r < 4; ++r) d[mi][ni][r] = 0.f;

        const int r0a = mbase + g,      r1a = mbase + g + 8;
        const int r0b = mbase + 16 + g, r1b = mbase + 24 + g;
        float af[2][4];
        {
            const float* p = w_atlas + tg;
            af[0][0] = p[r0a * 896];     af[0][1] = p[r1a * 896];
            af[0][2] = p[r0a * 896 + 4]; af[0][3] = p[r1a * 896 + 4];
            af[1][0] = p[r0b * 896];     af[1][1] = p[r1b * 896];
            af[1][2] = p[r0b * 896 + 4]; af[1][3] = p[r1b * 896 + 4];
        }
        #pragma unroll 1
        for (int ks = 0; ks < 112; ++ks) {
            unsigned a[2][4];
            #pragma unroll
            for (int mi = 0; mi < 2; ++mi)
                #pragma unroll
                for (int r = 0; r < 4; ++r) a[mi][r] = f2tf(af[mi][r]);
            if (ks < 111) {
                const float* p = w_atlas + (ks + 1) * 8 + tg;
                af[0][0] = p[r0a * 896];     af[0][1] = p[r1a * 896];
                af[0][2] = p[r0a * 896 + 4]; af[0][3] = p[r1a * 896 + 4];
                af[1][0] = p[r0b * 896];     af[1][1] = p[r1b * 896];
                af[1][2] = p[r0b * 896 + 4]; af[1][3] = p[r1b * 896 + 4];
            }
            const int k0 = ks * 8 + tg, k1 = k0 + 4;
            const int ie0 = k0 / 7, dk0 = k0 % 7;
            const int ie1 = k1 / 7, dk1 = k1 % 7;
            const unsigned* B0 = SHb + ie0 * 72 + g + dk0;  // h1T[ie0][a+dk0-3], a = ni*8+g
            const unsigned* B1 = SHb + ie1 * 72 + g + dk1;
            #pragma unroll
            for (int ni = 0; ni < 8; ++ni) {
                unsigned b[2] = { B0[ni * 8], B1[ni * 8] };
                mma_tf32(d[0][ni], a[0], b);
                mma_tf32(d[1][ni], a[1], b);
            }
        }
        // epilogue: + bias, SiLU, sum over valid a (<56), quad-reduce, store Sq
        #pragma unroll
        for (int mi = 0; mi < 2; ++mi)
            #pragma unroll
            for (int r2 = 0; r2 < 2; ++r2) {
                int oe = mbase + mi * 16 + g + r2 * 8;
                float bias = b_atlas[oe];
                float s = 0.f;
                #pragma unroll
                for (int ni = 0; ni < 7; ++ni) {   // a = ni*8+2tg+c; ni==7 -> a>=56 invalid
                    s += silu_f(d[mi][ni][r2 * 2 + 0] + bias);
                    s += silu_f(d[mi][ni][r2 * 2 + 1] + bias);
                }
                s += __shfl_xor_sync(0xffffffffu, s, 1);
                s += __shfl_xor_sync(0xffffffffu, s, 2);
                if (tg == 0) Sq[batch * 128 + oe] = s;
            }
    }
    __syncthreads();

    // ================ k-proj: D[o 128, (b,l) 128] = Wk[128,128] x x^T ====================
    {
        const int mg = wid & 3, batch = wid >> 2;
        const int mbase = mg * 32;
        const unsigned* SXb = SX + batch * SX_BSTRIDE;

        float d[2][8][4];
        #pragma unroll
        for (int mi = 0; mi < 2; ++mi)
            #pragma unroll
            for (int ni = 0; ni < 8; ++ni)
                #pragma unroll
                for (int r = 0; r < 4; ++r) d[mi][ni][r] = 0.f;

        const int r0a = mbase + g,      r1a = mbase + g + 8;
        const int r0b = mbase + 16 + g, r1b = mbase + 24 + g;
        float af[2][4];
        {
            const float* p = w_k + tg;
            af[0][0] = p[r0a * 128];     af[0][1] = p[r1a * 128];
            af[0][2] = p[r0a * 128 + 4]; af[0][3] = p[r1a * 128 + 4];
            af[1][0] = p[r0b * 128];     af[1][1] = p[r1b * 128];
            af[1][2] = p[r0b * 128 + 4]; af[1][3] = p[r1b * 128 + 4];
        }
        #pragma unroll 1
        for (int ks = 0; ks < 16; ++ks) {
            unsigned a[2][4];
            #pragma unroll
            for (int mi = 0; mi < 2; ++mi)
                #pragma unroll
                for (int r = 0; r < 4; ++r) a[mi][r] = f2tf(af[mi][r]);
            if (ks < 15) {
                const float* p = w_k + (ks + 1) * 8 + tg;
                af[0][0] = p[r0a * 128];     af[0][1] = p[r1a * 128];
                af[0][2] = p[r0a * 128 + 4]; af[0][3] = p[r1a * 128 + 4];
                af[1][0] = p[r0b * 128];     af[1][1] = p[r1b * 128];
                af[1][2] = p[r0b * 128 + 4]; af[1][3] = p[r1b * 128 + 4];
            }
            const unsigned* Bp = SXb + g * 134 + 3 + ks * 8 + tg;  // row l=ni*8+g, col e
            #pragma unroll
            for (int ni = 0; ni < 8; ++ni) {
                unsigned b[2] = { Bp[ni * 8 * 134], Bp[ni * 8 * 134 + 4] };
                mma_tf32(d[0][ni], a[0], b);
                mma_tf32(d[1][ni], a[1], b);
            }
        }
        __syncthreads();   // conv2 reads of SH1 are done (sync above), safe to overwrite as SK
        #pragma unroll
        for (int mi = 0; mi < 2; ++mi)
            #pragma unroll
            for (int r2 = 0; r2 < 2; ++r2) {
                int o = mbase + mi * 16 + g + r2 * 8;
                #pragma unroll
                for (int ni = 0; ni < 8; ++ni)
                    #pragma unroll
                    for (int c = 0; c < 2; ++c) {
                        int l = ni * 8 + tg * 2 + c;
                        SK[batch * SK_BSTRIDE + l * 132 + o] = d[mi][ni][r2 * 2 + c];
                    }
            }
    }
    __syncthreads();

    // ================ layernorms ================
    if (t < 16) {          // q LN: 2 batches x 8 heads
        const int batch = t >> 3, h = t & 7;
        float qv[16];
        float m = 0.f;
        #pragma unroll
        for (int d = 0; d < 16; ++d) {
            qv[d] = Sq[batch * 128 + h * 16 + d] * (1.0f / 56.0f);
            m += qv[d];
        }
        m *= (1.0f / 16.0f);
        float var = 0.f;
        #pragma unroll
        for (int d = 0; d < 16; ++d) { float dd = qv[d] - m; var += dd * dd; }
        var *= (1.0f / 16.0f);
        float rs = rsqrtf(var + LN_EPS);
        #pragma unroll
        for (int d = 0; d < 16; ++d)
            Sqn[batch * 128 + h * 16 + d] = ((qv[d] - m) * rs * qn_w[d] + qn_b[d]) * SCALING;
    }
    for (int i = t; i < 896; i += 256) {   // k LN: 2 x 56 x 8 groups
        const int batch = (i >= 448) ? 1 : 0;
        const int g2 = i - batch * 448;
        const int l = g2 >> 3, h = g2 & 7;
        float* kp = SK + batch * SK_BSTRIDE + l * 132 + h * 16;
        float m = 0.f;
        #pragma unroll
        for (int d = 0; d < 16; ++d) m += kp[d];
        m *= (1.0f / 16.0f);
        float var = 0.f;
        #pragma unroll
        for (int d = 0; d < 16; ++d) { float dd = kp[d] - m; var += dd * dd; }
        var *= (1.0f / 16.0f);
        float rs = rsqrtf(var + LN_EPS);
        #pragma unroll
        for (int d = 0; d < 16; ++d)
            kp[d] = (kp[d] - m) * rs * kn_w[d] + kn_b[d];
    }
    __syncthreads();

    // ================ attention logits + softmax ================
    for (int i = t; i < 896; i += 256) {
        const int batch = (i >= 448) ? 1 : 0;
        const int g2 = i - batch * 448;
        const int l = g2 >> 3, h = g2 & 7;
        const float* qp = Sqn + batch * 128 + h * 16;
        const float* kp = SK + batch * SK_BSTRIDE + l * 132 + h * 16;
        float s = 0.f;
        #pragma unroll
        for (int d = 0; d < 16; ++d) s += qp[d] * kp[d];
        SA[batch * 480 + h * 60 + l] = s;
    }
    __syncthreads();
    if (t < 16) {
        const int batch = t >> 3, h = t & 7;
        float* row = SA + batch * 480 + h * 60;
        float mx = -1e30f;
        for (int l = 0; l < 56; ++l) mx = fmaxf(mx, row[l]);
        float sum = 0.f;
        for (int l = 0; l < 56; ++l) { float e = __expf(row[l] - mx); row[l] = e; sum += e; }
        float inv = 1.0f / sum;
        for (int l = 0; l < 56; ++l) row[l] *= inv;
    }
    __syncthreads();
    if (t < 8) {
        const int batch = t >> 2, hh = t & 3;
        const float lam = Ssc[0];
        const float* p0 = SA + batch * 480 + (2 * hh) * 60;
        const float* p1 = SA + batch * 480 + (2 * hh + 1) * 60;
        float* dst = SA2 + batch * 240 + hh * 60;
        float mx = -1e30f;
        for (int l = 0; l < 56; ++l) {
            float v = p0[l] - lam * p1[l];
            dst[l] = v;
            mx = fmaxf(mx, v);
        }
        float sum = 0.f;
        for (int l = 0; l < 56; ++l) { float e = __expf(dst[l] - mx); dst[l] = e; sum += e; }
        float inv = 1.0f / sum;
        for (int l = 0; l < 56; ++l) dst[l] *= inv;
    }
    __syncthreads();
    if (t < 112) {
        const int batch = (t >= 56) ? 1 : 0;
        const int l = t - batch * 56;
        const float* base = SA2 + batch * 240;
        out[((size_t)blockIdx.x * 2 + batch) * 56 + l] =
            0.25f * (base[l] + base[60 + l] + base[120 + l] + base[180 + l]);
    }
}

extern "C" void kernel_launch(void* const* d_in, const int* in_sizes, int n_in,
                              void* d_out, int out_size) {
    const float* x       = (const float*)d_in[0];
    const float* w_emb   = (const float*)d_in[1];
    const float* b_emb   = (const float*)d_in[2];
    const float* w_atlas = (const float*)d_in[3];
    const float* b_atlas = (const float*)d_in[4];
    const float* w_k     = (const float*)d_in[5];
    const float* qn_w    = (const float*)d_in[6];
    const float* qn_b    = (const float*)d_in[7];
    const float* kn_w    = (const float*)d_in[8];
    const float* kn_b    = (const float*)d_in[9];
    const float* lq1     = (const float*)d_in[10];
    const float* lk1     = (const float*)d_in[11];
    const float* lq2     = (const float*)d_in[12];
    const float* lk2     = (const float*)d_in[13];
    float* out = (float*)d_out;

    const int B = in_sizes[0] / (A_DIM * E_DIM);
    const size_t smem = SMEM_WORDS * sizeof(unsigned);
    cudaFuncSetAttribute(atlas_mdattn_tc,
                         cudaFuncAttributeMaxDynamicSharedMemorySize, (int)smem);
    atlas_mdattn_tc<<<B / 2, 256, smem>>>(
        x, w_emb, b_emb, w_atlas, b_atlas, w_k,
        qn_w, qn_b, kn_w, kn_b, lq1, lk1, lq2, lk2, out);
}

// round 3
// speedup vs baseline: 2.9952x; 1.1184x over previous
#include <cuda_runtime.h>
#include <math.h>

// ---- problem constants ----
#define A_DIM 56
#define E_DIM 128
#define LAMBDA_INIT 0.7f
#define LN_EPS 1e-5f
#define SCALING 0.25f   // HD^-0.5, HD=16

// ---- repacked weight sizes (32-bit words) ----
#define W1_WORDS (2 * 49 * 256)    // conv1: 2 m-groups, K=392 (49 ksteps)
#define W2_WORDS (4 * 112 * 256)   // conv2: 4 m-groups, K=896 (112 ksteps)
#define W3_WORDS (4 * 16 * 256)    // kproj: 4 m-groups, K=128 (16 ksteps)
#define W_TOTAL  (W1_WORDS + W2_WORDS + W3_WORDS)

__device__ __align__(16) unsigned g_w1[W1_WORDS];
__device__ __align__(16) unsigned g_w2[W2_WORDS];
__device__ __align__(16) unsigned g_w3[W3_WORDS];

// ---- smem layout (32-bit words) ----
#define SX_BSTRIDE (64 * 134)      // [2][64][134] tf32 x, halo-padded
#define SZ_SX      (2 * SX_BSTRIDE)
#define SH1_BSTRIDE (128 * 72)     // [2][128][72] tf32 h1^T; reused as SK fp32 [2][64][132]
#define SZ_SH1      (2 * SH1_BSTRIDE)
#define SK_BSTRIDE  (64 * 132)

#define OFF_SX   0
#define OFF_SH1  (OFF_SX + SZ_SX)
#define OFF_SQ   (OFF_SH1 + SZ_SH1)
#define OFF_SQN  (OFF_SQ + 256)
#define OFF_SA   (OFF_SQN + 256)
#define OFF_SA2  (OFF_SA + 960)
#define OFF_SC   (OFF_SA2 + 480)
#define SMEM_WORDS (OFF_SC + 4)

__device__ __forceinline__ unsigned f2tf(float f) {
    unsigned u;
    asm("cvt.rna.tf32.f32 %0, %1;" : "=r"(u) : "f"(f));
    return u;
}
__device__ __forceinline__ float silu_f(float v) {
    return v / (1.0f + __expf(-v));
}
__device__ __forceinline__ void mma_tf32(float* d, const unsigned* a, const unsigned* b) {
    asm volatile(
        "mma.sync.aligned.m16n8k8.row.col.f32.tf32.tf32.f32 "
        "{%0,%1,%2,%3}, {%4,%5,%6,%7}, {%8,%9}, {%0,%1,%2,%3};"
        : "+f"(d[0]), "+f"(d[1]), "+f"(d[2]), "+f"(d[3])
        : "r"(a[0]), "r"(a[1]), "r"(a[2]), "r"(a[3]), "r"(b[0]), "r"(b[1]));
}

// ================== weight repack: fragment-order tf32 ==================
// Layout per m-group block: word index = ks*256 + j2*64 + lane*2 + p,
// where j = 2*j2+p, mi = j>>2, r = j&3,
// row = mg*32 + mi*16 + g + (r&1)*8, col = ks*8 + tg + (r>=2)*4,
// g = lane>>2, tg = lane&3.
__global__ void __launch_bounds__(256)
repack_kernel(const float* __restrict__ w_emb,
              const float* __restrict__ w_atlas,
              const float* __restrict__ w_k)
{
    int i = blockIdx.x * 256 + threadIdx.x;
    if (i >= W_TOTAL) return;

    const float* src;
    unsigned* dst;
    int K, src_stride, row_lim, ii;
    if (i < W1_WORDS) {
        ii = i; src = w_emb; dst = g_w1; K = 49; src_stride = 392; row_lim = 56;
    } else if (i < W1_WORDS + W2_WORDS) {
        ii = i - W1_WORDS; src = w_atlas; dst = g_w2; K = 112; src_stride = 896; row_lim = 128;
    } else {
        ii = i - W1_WORDS - W2_WORDS; src = w_k; dst = g_w3; K = 16; src_stride = 128; row_lim = 128;
    }
    int p    = ii & 1;
    int lane = (ii >> 1) & 31;
    int j2   = (ii >> 6) & 3;
    int blk  = ii >> 8;            // mg*K + ks
    int ks   = blk % K;
    int mg   = blk / K;
    int j    = j2 * 2 + p;
    int mi   = j >> 2, r = j & 3;
    int g = lane >> 2, tg = lane & 3;
    int row = mg * 32 + mi * 16 + g + ((r & 1) ? 8 : 0);
    int col = ks * 8 + tg + ((r >= 2) ? 4 : 0);
    float v = (row < row_lim) ? src[row * src_stride + col] : 0.f;
    dst[ii] = f2tf(v);
}

extern __shared__ unsigned smw[];

__global__ void __launch_bounds__(256, 1)
atlas_mdattn_tc(
    const float* __restrict__ x,       // [B,56,128]
    const float* __restrict__ b_emb,   // [56]
    const float* __restrict__ b_atlas, // [128]
    const float* __restrict__ qn_w, const float* __restrict__ qn_b,
    const float* __restrict__ kn_w, const float* __restrict__ kn_b,
    const float* __restrict__ lq1, const float* __restrict__ lk1,
    const float* __restrict__ lq2, const float* __restrict__ lk2,
    float* __restrict__ out)           // [B,56]
{
    const int t = threadIdx.x;
    const int lane = t & 31, wid = t >> 5;
    const int g = lane >> 2, tg = lane & 3;

    unsigned* SX  = smw + OFF_SX;
    unsigned* SH1 = smw + OFF_SH1;
    float* Sq  = (float*)(smw + OFF_SQ);
    float* Sqn = (float*)(smw + OFF_SQN);
    float* SA  = (float*)(smw + OFF_SA);
    float* SA2 = (float*)(smw + OFF_SA2);
    float* Ssc = (float*)(smw + OFF_SC);
    float* SK  = (float*)SH1;

    // ---------------- init ----------------
    {
        uint4 z = make_uint4(0, 0, 0, 0);
        uint4* p = (uint4*)smw;
        for (int i = t; i < (SZ_SX + SZ_SH1) / 4; i += 256) p[i] = z;
    }
    if (t == 0) {
        float s1 = 0.f, s2 = 0.f;
        #pragma unroll
        for (int d = 0; d < 16; ++d) { s1 += lq1[d] * lk1[d]; s2 += lq2[d] * lk2[d]; }
        Ssc[0] = __expf(s1) - __expf(s2) + LAMBDA_INIT;
    }
    __syncthreads();

    // load x (2 batches), tf32, halo-padded
    const float* xb = x + (size_t)blockIdx.x * 2 * (A_DIM * E_DIM);
    #pragma unroll
    for (int bb = 0; bb < 2; ++bb) {
        for (int i = t; i < A_DIM * E_DIM; i += 256) {
            int l = i >> 7, e = i & 127;
            SX[bb * SX_BSTRIDE + l * 134 + 3 + e] = f2tf(xb[bb * A_DIM * E_DIM + i]);
        }
    }
    __syncthreads();

    // ============ conv1: D[oa 64, (b,e) 256] = Wemb x im2col(x), K=392 ============
    {
        const int mg = wid & 1, ng = wid >> 1;
        const int mbase = mg * 32;
        const int batch = ng >> 1;
        const int ebase = (ng * 64) & 127;
        const unsigned* SXb = SX + batch * SX_BSTRIDE;
        const uint2* Wp = (const uint2*)(g_w1 + mg * (49 * 256));

        float d[2][8][4];
        #pragma unroll
        for (int mi = 0; mi < 2; ++mi)
            #pragma unroll
            for (int ni = 0; ni < 8; ++ni)
                #pragma unroll
                for (int r = 0; r < 4; ++r) d[mi][ni][r] = 0.f;

        uint2 P[2][4];
        #pragma unroll
        for (int s = 0; s < 2; ++s)
            #pragma unroll
            for (int j2 = 0; j2 < 4; ++j2)
                P[s][j2] = Wp[s * 128 + j2 * 32 + lane];

        #pragma unroll 1
        for (int ks = 0; ks < 49; ++ks) {
            const int sb = ks & 1;
            unsigned a0[4] = { P[sb][0].x, P[sb][0].y, P[sb][1].x, P[sb][1].y };
            unsigned a1[4] = { P[sb][2].x, P[sb][2].y, P[sb][3].x, P[sb][3].y };
            if (ks + 2 < 49) {
                #pragma unroll
                for (int j2 = 0; j2 < 4; ++j2)
                    P[sb][j2] = Wp[(ks + 2) * 128 + j2 * 32 + lane];
            }
            const int k0 = ks * 8 + tg, k1 = k0 + 4;
            const int ia0 = k0 / 7, dk0 = k0 % 7;
            const int ia1 = k1 / 7, dk1 = k1 % 7;
            const unsigned* B0 = SXb + ia0 * 134 + ebase + g + dk0;
            const unsigned* B1 = SXb + ia1 * 134 + ebase + g + dk1;
            #pragma unroll
            for (int ni = 0; ni < 8; ++ni) {
                unsigned b[2] = { B0[ni * 8], B1[ni * 8] };
                mma_tf32(d[0][ni], a0, b);
                mma_tf32(d[1][ni], a1, b);
            }
        }
        // epilogue: bias + SiLU, store transposed tf32 into SH1[batch][e][oa+3]
        #pragma unroll
        for (int mi = 0; mi < 2; ++mi)
            #pragma unroll
            for (int r2 = 0; r2 < 2; ++r2) {
                int oa = mbase + mi * 16 + g + r2 * 8;
                if (oa < 56) {
                    float bias = b_emb[oa];
                    #pragma unroll
                    for (int ni = 0; ni < 8; ++ni)
                        #pragma unroll
                        for (int c = 0; c < 2; ++c) {
                            int e = ebase + ni * 8 + tg * 2 + c;
                            float v = silu_f(d[mi][ni][r2 * 2 + c] + bias);
                            SH1[batch * SH1_BSTRIDE + e * 72 + oa + 3] = f2tf(v);
                        }
                }
            }
    }
    __syncthreads();

    // ============ conv2: D[oe 128, (b,a) 128] = Watlas x im2col(h1T), K=896 ============
    {
        const int mg = wid & 3, batch = wid >> 2;
        const int mbase = mg * 32;
        const unsigned* SHb = SH1 + batch * SH1_BSTRIDE;
        const uint2* Wp = (const uint2*)(g_w2 + mg * (112 * 256));

        float d[2][8][4];
        #pragma unroll
        for (int mi = 0; mi < 2; ++mi)
            #pragma unroll
            for (int ni = 0; ni < 8; ++ni)
                #pragma unroll
                for (int r = 0; r < 4; ++r) d[mi][ni][r] = 0.f;

        uint2 P[2][4];
        #pragma unroll
        for (int s = 0; s < 2; ++s)
            #pragma unroll
            for (int j2 = 0; j2 < 4; ++j2)
                P[s][j2] = Wp[s * 128 + j2 * 32 + lane];

        #pragma unroll 1
        for (int ks = 0; ks < 112; ++ks) {
            const int sb = ks & 1;
            unsigned a0[4] = { P[sb][0].x, P[sb][0].y, P[sb][1].x, P[sb][1].y };
            unsigned a1[4] = { P[sb][2].x, P[sb][2].y, P[sb][3].x, P[sb][3].y };
            if (ks + 2 < 112) {
                #pragma unroll
                for (int j2 = 0; j2 < 4; ++j2)
                    P[sb][j2] = Wp[(ks + 2) * 128 + j2 * 32 + lane];
            }
            const int k0 = ks * 8 + tg, k1 = k0 + 4;
            const int ie0 = k0 / 7, dk0 = k0 % 7;
            const int ie1 = k1 / 7, dk1 = k1 % 7;
            const unsigned* B0 = SHb + ie0 * 72 + g + dk0;
            const unsigned* B1 = SHb + ie1 * 72 + g + dk1;
            #pragma unroll
            for (int ni = 0; ni < 8; ++ni) {
                unsigned b[2] = { B0[ni * 8], B1[ni * 8] };
                mma_tf32(d[0][ni], a0, b);
                mma_tf32(d[1][ni], a1, b);
            }
        }
        // epilogue: bias + SiLU + masked sum over a + quad reduce -> Sq
        #pragma unroll
        for (int mi = 0; mi < 2; ++mi)
            #pragma unroll
            for (int r2 = 0; r2 < 2; ++r2) {
                int oe = mbase + mi * 16 + g + r2 * 8;
                float bias = b_atlas[oe];
                float s = 0.f;
                #pragma unroll
                for (int ni = 0; ni < 7; ++ni) {
                    s += silu_f(d[mi][ni][r2 * 2 + 0] + bias);
                    s += silu_f(d[mi][ni][r2 * 2 + 1] + bias);
                }
                s += __shfl_xor_sync(0xffffffffu, s, 1);
                s += __shfl_xor_sync(0xffffffffu, s, 2);
                if (tg == 0) Sq[batch * 128 + oe] = s;
            }
    }
    __syncthreads();

    // ============ k-proj: D[o 128, (b,l) 128] = Wk x x^T, K=128 ============
    {
        const int mg = wid & 3, batch = wid >> 2;
        const int mbase = mg * 32;
        const unsigned* SXb = SX + batch * SX_BSTRIDE;
        const uint2* Wp = (const uint2*)(g_w3 + mg * (16 * 256));

        float d[2][8][4];
        #pragma unroll
        for (int mi = 0; mi < 2; ++mi)
            #pragma unroll
            for (int ni = 0; ni < 8; ++ni)
                #pragma unroll
                for (int r = 0; r < 4; ++r) d[mi][ni][r] = 0.f;

        uint2 P[2][4];
        #pragma unroll
        for (int s = 0; s < 2; ++s)
            #pragma unroll
            for (int j2 = 0; j2 < 4; ++j2)
                P[s][j2] = Wp[s * 128 + j2 * 32 + lane];

        #pragma unroll 1
        for (int ks = 0; ks < 16; ++ks) {
            const int sb = ks & 1;
            unsigned a0[4] = { P[sb][0].x, P[sb][0].y, P[sb][1].x, P[sb][1].y };
            unsigned a1[4] = { P[sb][2].x, P[sb][2].y, P[sb][3].x, P[sb][3].y };
            if (ks + 2 < 16) {
                #pragma unroll
                for (int j2 = 0; j2 < 4; ++j2)
                    P[sb][j2] = Wp[(ks + 2) * 128 + j2 * 32 + lane];
            }
            const unsigned* Bp = SXb + g * 134 + 3 + ks * 8 + tg;
            #pragma unroll
            for (int ni = 0; ni < 8; ++ni) {
                unsigned b[2] = { Bp[ni * 8 * 134], Bp[ni * 8 * 134 + 4] };
                mma_tf32(d[0][ni], a0, b);
                mma_tf32(d[1][ni], a1, b);
            }
        }
        __syncthreads();   // conv2 reads of SH1 done; safe to overwrite as SK
        #pragma unroll
        for (int mi = 0; mi < 2; ++mi)
            #pragma unroll
            for (int r2 = 0; r2 < 2; ++r2) {
                int o = mbase + mi * 16 + g + r2 * 8;
                #pragma unroll
                for (int ni = 0; ni < 8; ++ni)
                    #pragma unroll
                    for (int c = 0; c < 2; ++c) {
                        int l = ni * 8 + tg * 2 + c;
                        SK[batch * SK_BSTRIDE + l * 132 + o] = d[mi][ni][r2 * 2 + c];
                    }
            }
    }
    __syncthreads();

    // ================ layernorms ================
    if (t < 16) {
        const int batch = t >> 3, h = t & 7;
        float qv[16];
        float m = 0.f;
        #pragma unroll
        for (int d = 0; d < 16; ++d) {
            qv[d] = Sq[batch * 128 + h * 16 + d] * (1.0f / 56.0f);
            m += qv[d];
        }
        m *= (1.0f / 16.0f);
        float var = 0.f;
        #pragma unroll
        for (int d = 0; d < 16; ++d) { float dd = qv[d] - m; var += dd * dd; }
        var *= (1.0f / 16.0f);
        float rs = rsqrtf(var + LN_EPS);
        #pragma unroll
        for (int d = 0; d < 16; ++d)
            Sqn[batch * 128 + h * 16 + d] = ((qv[d] - m) * rs * qn_w[d] + qn_b[d]) * SCALING;
    }
    for (int i = t; i < 896; i += 256) {
        const int batch = (i >= 448) ? 1 : 0;
        const int g2 = i - batch * 448;
        const int l = g2 >> 3, h = g2 & 7;
        float* kp = SK + batch * SK_BSTRIDE + l * 132 + h * 16;
        float m = 0.f;
        #pragma unroll
        for (int d = 0; d < 16; ++d) m += kp[d];
        m *= (1.0f / 16.0f);
        float var = 0.f;
        #pragma unroll
        for (int d = 0; d < 16; ++d) { float dd = kp[d] - m; var += dd * dd; }
        var *= (1.0f / 16.0f);
        float rs = rsqrtf(var + LN_EPS);
        #pragma unroll
        for (int d = 0; d < 16; ++d)
            kp[d] = (kp[d] - m) * rs * kn_w[d] + kn_b[d];
    }
    __syncthreads();

    // ================ attention + double softmax ================
    for (int i = t; i < 896; i += 256) {
        const int batch = (i >= 448) ? 1 : 0;
        const int g2 = i - batch * 448;
        const int l = g2 >> 3, h = g2 & 7;
        const float* qp = Sqn + batch * 128 + h * 16;
        const float* kp = SK + batch * SK_BSTRIDE + l * 132 + h * 16;
        float s = 0.f;
        #pragma unroll
        for (int d = 0; d < 16; ++d) s += qp[d] * kp[d];
        SA[batch * 480 + h * 60 + l] = s;
    }
    __syncthreads();
    if (t < 16) {
        const int batch = t >> 3, h = t & 7;
        float* row = SA + batch * 480 + h * 60;
        float mx = -1e30f;
        for (int l = 0; l < 56; ++l) mx = fmaxf(mx, row[l]);
        float sum = 0.f;
        for (int l = 0; l < 56; ++l) { float e = __expf(row[l] - mx); row[l] = e; sum += e; }
        float inv = 1.0f / sum;
        for (int l = 0; l < 56; ++l) row[l] *= inv;
    }
    __syncthreads();
    if (t < 8) {
        const int batch = t >> 2, hh = t & 3;
        const float lam = Ssc[0];
        const float* p0 = SA + batch * 480 + (2 * hh) * 60;
        const float* p1 = SA + batch * 480 + (2 * hh + 1) * 60;
        float* dst = SA2 + batch * 240 + hh * 60;
        float mx = -1e30f;
        for (int l = 0; l < 56; ++l) {
            float v = p0[l] - lam * p1[l];
            dst[l] = v;
            mx = fmaxf(mx, v);
        }
        float sum = 0.f;
        for (int l = 0; l < 56; ++l) { float e = __expf(dst[l] - mx); dst[l] = e; sum += e; }
        float inv = 1.0f / sum;
        for (int l = 0; l < 56; ++l) dst[l] *= inv;
    }
    __syncthreads();
    if (t < 112) {
        const int batch = (t >= 56) ? 1 : 0;
        const int l = t - batch * 56;
        const float* base = SA2 + batch * 240;
        out[((size_t)blockIdx.x * 2 + batch) * 56 + l] =
            0.25f * (base[l] + base[60 + l] + base[120 + l] + base[180 + l]);
    }
}

extern "C" void kernel_launch(void* const* d_in, const int* in_sizes, int n_in,
                              void* d_out, int out_size) {
    const float* x       = (const float*)d_in[0];
    const float* w_emb   = (const float*)d_in[1];
    const float* b_emb   = (const float*)d_in[2];
    const float* w_atlas = (const float*)d_in[3];
    const float* b_atlas = (const float*)d_in[4];
    const float* w_k     = (const float*)d_in[5];
    const float* qn_w    = (const float*)d_in[6];
    const float* qn_b    = (const float*)d_in[7];
    const float* kn_w    = (const float*)d_in[8];
    const float* kn_b    = (const float*)d_in[9];
    const float* lq1     = (const float*)d_in[10];
    const float* lk1     = (const float*)d_in[11];
    const float* lq2     = (const float*)d_in[12];
    const float* lk2     = (const float*)d_in[13];
    float* out = (float*)d_out;

    const int B = in_sizes[0] / (A_DIM * E_DIM);

    repack_kernel<<<(W_TOTAL + 255) / 256, 256>>>(w_emb, w_atlas, w_k);

    const size_t smem = SMEM_WORDS * sizeof(unsigned);
    cudaFuncSetAttribute(atlas_mdattn_tc,
                         cudaFuncAttributeMaxDynamicSharedMemorySize, (int)smem);
    atlas_mdattn_tc<<<B / 2, 256, smem>>>(
        x, b_emb, b_atlas,
        qn_w, qn_b, kn_w, kn_b, lq1, lk1, lq2, lk2, out);
}

// round 4
// speedup vs baseline: 3.0004x; 1.0017x over previous
#include <cuda_runtime.h>
#include <math.h>

// ---- problem constants ----
#define A_DIM 56
#define E_DIM 128
#define LAMBDA_INIT 0.7f
#define LN_EPS 1e-5f
#define SCALING 0.25f   // HD^-0.5, HD=16

// ---- repacked weight sizes (32-bit words) ----
#define W1_WORDS (2 * 49 * 256)    // conv1: 2 m-groups, K=392 (49 ksteps)
#define W2_WORDS (4 * 112 * 256)   // conv2: 4 m-groups, K=896 (112 ksteps)
#define W3_WORDS (4 * 16 * 256)    // kproj: 4 m-groups, K=128 (16 ksteps)
#define W_TOTAL  (W1_WORDS + W2_WORDS + W3_WORDS)

__device__ __align__(16) unsigned g_w1[W1_WORDS];
__device__ __align__(16) unsigned g_w2[W2_WORDS];
__device__ __align__(16) unsigned g_w3[W3_WORDS];

// ---- smem layout (32-bit words) ----
#define SX_BSTRIDE (64 * 134)      // [2][64][134] tf32 x, halo-padded
#define SZ_SX      (2 * SX_BSTRIDE)
#define SH1_BSTRIDE (128 * 72)     // [2][128][72] tf32 h1^T; reused as SK fp32 [2][64][132]
#define SZ_SH1      (2 * SH1_BSTRIDE)
#define SK_BSTRIDE  (64 * 132)

#define OFF_SX   0
#define OFF_SH1  (OFF_SX + SZ_SX)
#define OFF_SQ   (OFF_SH1 + SZ_SH1)
#define OFF_SQN  (OFF_SQ + 256)
#define OFF_SA   (OFF_SQN + 256)
#define OFF_SA2  (OFF_SA + 960)
#define OFF_SC   (OFF_SA2 + 480)
#define SMEM_WORDS (OFF_SC + 4)

__device__ __forceinline__ unsigned f2tf(float f) {
    unsigned u;
    asm("cvt.rna.tf32.f32 %0, %1;" : "=r"(u) : "f"(f));
    return u;
}
__device__ __forceinline__ float silu_f(float v) {
    return v / (1.0f + __expf(-v));
}
__device__ __forceinline__ void mma_tf32(float* d, const unsigned* a, const unsigned* b) {
    asm volatile(
        "mma.sync.aligned.m16n8k8.row.col.f32.tf32.tf32.f32 "
        "{%0,%1,%2,%3}, {%4,%5,%6,%7}, {%8,%9}, {%0,%1,%2,%3};"
        : "+f"(d[0]), "+f"(d[1]), "+f"(d[2]), "+f"(d[3])
        : "r"(a[0]), "r"(a[1]), "r"(a[2]), "r"(a[3]), "r"(b[0]), "r"(b[1]));
}

// ================== weight repack: fragment-order tf32 ==================
__global__ void __launch_bounds__(256)
repack_kernel(const float* __restrict__ w_emb,
              const float* __restrict__ w_atlas,
              const float* __restrict__ w_k)
{
    int i = blockIdx.x * 256 + threadIdx.x;
    if (i >= W_TOTAL) return;

    const float* src;
    unsigned* dst;
    int K, src_stride, row_lim, ii;
    if (i < W1_WORDS) {
        ii = i; src = w_emb; dst = g_w1; K = 49; src_stride = 392; row_lim = 56;
    } else if (i < W1_WORDS + W2_WORDS) {
        ii = i - W1_WORDS; src = w_atlas; dst = g_w2; K = 112; src_stride = 896; row_lim = 128;
    } else {
        ii = i - W1_WORDS - W2_WORDS; src = w_k; dst = g_w3; K = 16; src_stride = 128; row_lim = 128;
    }
    int p    = ii & 1;
    int lane = (ii >> 1) & 31;
    int j2   = (ii >> 6) & 3;
    int blk  = ii >> 8;            // mg*K + ks
    int ks   = blk % K;
    int mg   = blk / K;
    int j    = j2 * 2 + p;
    int mi   = j >> 2, r = j & 3;
    int g = lane >> 2, tg = lane & 3;
    int row = mg * 32 + mi * 16 + g + ((r & 1) ? 8 : 0);
    int col = ks * 8 + tg + ((r >= 2) ? 4 : 0);
    float v = (row < row_lim) ? src[row * src_stride + col] : 0.f;
    dst[ii] = f2tf(v);
}

extern __shared__ unsigned smw[];

__global__ void __launch_bounds__(256, 1)
atlas_mdattn_tc(
    const float* __restrict__ x,       // [B,56,128]
    const float* __restrict__ b_emb,   // [56]
    const float* __restrict__ b_atlas, // [128]
    const float* __restrict__ qn_w, const float* __restrict__ qn_b,
    const float* __restrict__ kn_w, const float* __restrict__ kn_b,
    const float* __restrict__ lq1, const float* __restrict__ lk1,
    const float* __restrict__ lq2, const float* __restrict__ lk2,
    float* __restrict__ out)           // [B,56]
{
    const int t = threadIdx.x;
    const int lane = t & 31, wid = t >> 5;
    const int g = lane >> 2, tg = lane & 3;

    unsigned* SX  = smw + OFF_SX;
    unsigned* SH1 = smw + OFF_SH1;
    float* Sq  = (float*)(smw + OFF_SQ);
    float* Sqn = (float*)(smw + OFF_SQN);
    float* SA  = (float*)(smw + OFF_SA);
    float* SA2 = (float*)(smw + OFF_SA2);
    float* Ssc = (float*)(smw + OFF_SC);
    float* SK  = (float*)SH1;

    // ---------------- init ----------------
    {
        uint4 z = make_uint4(0, 0, 0, 0);
        uint4* p = (uint4*)smw;
        for (int i = t; i < (SZ_SX + SZ_SH1) / 4; i += 256) p[i] = z;
    }
    if (t == 0) {
        float s1 = 0.f, s2 = 0.f;
        #pragma unroll
        for (int d = 0; d < 16; ++d) { s1 += lq1[d] * lk1[d]; s2 += lq2[d] * lk2[d]; }
        Ssc[0] = __expf(s1) - __expf(s2) + LAMBDA_INIT;
    }
    __syncthreads();

    // load x (2 batches), tf32, halo-padded
    const float* xb = x + (size_t)blockIdx.x * 2 * (A_DIM * E_DIM);
    #pragma unroll
    for (int bb = 0; bb < 2; ++bb) {
        for (int i = t; i < A_DIM * E_DIM; i += 256) {
            int l = i >> 7, e = i & 127;
            SX[bb * SX_BSTRIDE + l * 134 + 3 + e] = f2tf(xb[bb * A_DIM * E_DIM + i]);
        }
    }
    __syncthreads();

    // ============ conv1: D[oa 64, (b,e) 256] = Wemb x im2col(x), K=392 ============
    {
        const int mg = wid & 1, ng = wid >> 1;
        const int mbase = mg * 32;
        const int batch = ng >> 1;
        const int ebase = (ng * 64) & 127;
        const unsigned* SXb = SX + batch * SX_BSTRIDE;
        const uint2* Wp = (const uint2*)(g_w1 + mg * (49 * 256));

        float d[2][8][4];
        #pragma unroll
        for (int mi = 0; mi < 2; ++mi)
            #pragma unroll
            for (int ni = 0; ni < 8; ++ni)
                #pragma unroll
                for (int r = 0; r < 4; ++r) d[mi][ni][r] = 0.f;

        uint2 P[4][4];
        #pragma unroll
        for (int s = 0; s < 4; ++s)
            #pragma unroll
            for (int j2 = 0; j2 < 4; ++j2)
                P[s][j2] = Wp[s * 128 + j2 * 32 + lane];

        #pragma unroll 1
        for (int ks = 0; ks < 49; ++ks) {
            const int sb = ks & 3;
            unsigned a0[4] = { P[sb][0].x, P[sb][0].y, P[sb][1].x, P[sb][1].y };
            unsigned a1[4] = { P[sb][2].x, P[sb][2].y, P[sb][3].x, P[sb][3].y };
            if (ks + 4 < 49) {
                #pragma unroll
                for (int j2 = 0; j2 < 4; ++j2)
                    P[sb][j2] = Wp[(ks + 4) * 128 + j2 * 32 + lane];
            }
            const int k0 = ks * 8 + tg, k1 = k0 + 4;
            const int ia0 = k0 / 7, dk0 = k0 % 7;
            const int ia1 = k1 / 7, dk1 = k1 % 7;
            const unsigned* B0 = SXb + ia0 * 134 + ebase + g + dk0;
            const unsigned* B1 = SXb + ia1 * 134 + ebase + g + dk1;
            #pragma unroll
            for (int ni = 0; ni < 8; ++ni) {
                unsigned b[2] = { B0[ni * 8], B1[ni * 8] };
                mma_tf32(d[0][ni], a0, b);
                mma_tf32(d[1][ni], a1, b);
            }
        }
        // epilogue: bias + SiLU, store transposed tf32 into SH1[batch][e][oa+3]
        #pragma unroll
        for (int mi = 0; mi < 2; ++mi)
            #pragma unroll
            for (int r2 = 0; r2 < 2; ++r2) {
                int oa = mbase + mi * 16 + g + r2 * 8;
                if (oa < 56) {
                    float bias = b_emb[oa];
                    #pragma unroll
                    for (int ni = 0; ni < 8; ++ni)
                        #pragma unroll
                        for (int c = 0; c < 2; ++c) {
                            int e = ebase + ni * 8 + tg * 2 + c;
                            float v = silu_f(d[mi][ni][r2 * 2 + c] + bias);
                            SH1[batch * SH1_BSTRIDE + e * 72 + oa + 3] = f2tf(v);
                        }
                }
            }
    }
    __syncthreads();

    // ============ conv2: D[oe 128, (b,a) 128] = Watlas x im2col(h1T), K=896 ============
    {
        const int mg = wid & 3, batch = wid >> 2;
        const int mbase = mg * 32;
        const unsigned* SHb = SH1 + batch * SH1_BSTRIDE;
        const uint2* Wp = (const uint2*)(g_w2 + mg * (112 * 256));

        float d[2][8][4];
        #pragma unroll
        for (int mi = 0; mi < 2; ++mi)
            #pragma unroll
            for (int ni = 0; ni < 8; ++ni)
                #pragma unroll
                for (int r = 0; r < 4; ++r) d[mi][ni][r] = 0.f;

        uint2 P[4][4];
        #pragma unroll
        for (int s = 0; s < 4; ++s)
            #pragma unroll
            for (int j2 = 0; j2 < 4; ++j2)
                P[s][j2] = Wp[s * 128 + j2 * 32 + lane];

        #pragma unroll 1
        for (int ks = 0; ks < 112; ++ks) {
            const int sb = ks & 3;
            unsigned a0[4] = { P[sb][0].x, P[sb][0].y, P[sb][1].x, P[sb][1].y };
            unsigned a1[4] = { P[sb][2].x, P[sb][2].y, P[sb][3].x, P[sb][3].y };
            if (ks + 4 < 112) {
                #pragma unroll
                for (int j2 = 0; j2 < 4; ++j2)
                    P[sb][j2] = Wp[(ks + 4) * 128 + j2 * 32 + lane];
            }
            const int k0 = ks * 8 + tg, k1 = k0 + 4;
            const int ie0 = k0 / 7, dk0 = k0 % 7;
            const int ie1 = k1 / 7, dk1 = k1 % 7;
            const unsigned* B0 = SHb + ie0 * 72 + g + dk0;
            const unsigned* B1 = SHb + ie1 * 72 + g + dk1;
            #pragma unroll
            for (int ni = 0; ni < 8; ++ni) {
                unsigned b[2] = { B0[ni * 8], B1[ni * 8] };
                mma_tf32(d[0][ni], a0, b);
                mma_tf32(d[1][ni], a1, b);
            }
        }
        // epilogue: bias + SiLU + masked sum over a + quad reduce -> Sq
        #pragma unroll
        for (int mi = 0; mi < 2; ++mi)
            #pragma unroll
            for (int r2 = 0; r2 < 2; ++r2) {
                int oe = mbase + mi * 16 + g + r2 * 8;
                float bias = b_atlas[oe];
                float s = 0.f;
                #pragma unroll
                for (int ni = 0; ni < 7; ++ni) {
                    s += silu_f(d[mi][ni][r2 * 2 + 0] + bias);
                    s += silu_f(d[mi][ni][r2 * 2 + 1] + bias);
                }
                s += __shfl_xor_sync(0xffffffffu, s, 1);
                s += __shfl_xor_sync(0xffffffffu, s, 2);
                if (tg == 0) Sq[batch * 128 + oe] = s;
            }
    }
    __syncthreads();

    // ============ k-proj: D[o 128, (b,l) 128] = Wk x x^T, K=128 ============
    {
        const int mg = wid & 3, batch = wid >> 2;
        const int mbase = mg * 32;
        const unsigned* SXb = SX + batch * SX_BSTRIDE;
        const uint2* Wp = (const uint2*)(g_w3 + mg * (16 * 256));

        float d[2][8][4];
        #pragma unroll
        for (int mi = 0; mi < 2; ++mi)
            #pragma unroll
            for (int ni = 0; ni < 8; ++ni)
                #pragma unroll
                for (int r = 0; r < 4; ++r) d[mi][ni][r] = 0.f;

        uint2 P[4][4];
        #pragma unroll
        for (int s = 0; s < 4; ++s)
            #pragma unroll
            for (int j2 = 0; j2 < 4; ++j2)
                P[s][j2] = Wp[s * 128 + j2 * 32 + lane];

        #pragma unroll 1
        for (int ks = 0; ks < 16; ++ks) {
            const int sb = ks & 3;
            unsigned a0[4] = { P[sb][0].x, P[sb][0].y, P[sb][1].x, P[sb][1].y };
            unsigned a1[4] = { P[sb][2].x, P[sb][2].y, P[sb][3].x, P[sb][3].y };
            if (ks + 4 < 16) {
                #pragma unroll
                for (int j2 = 0; j2 < 4; ++j2)
                    P[sb][j2] = Wp[(ks + 4) * 128 + j2 * 32 + lane];
            }
            const unsigned* Bp = SXb + g * 134 + 3 + ks * 8 + tg;
            #pragma unroll
            for (int ni = 0; ni < 8; ++ni) {
                unsigned b[2] = { Bp[ni * 8 * 134], Bp[ni * 8 * 134 + 4] };
                mma_tf32(d[0][ni], a0, b);
                mma_tf32(d[1][ni], a1, b);
            }
        }
        __syncthreads();   // conv2 reads of SH1 done; safe to overwrite as SK
        #pragma unroll
        for (int mi = 0; mi < 2; ++mi)
            #pragma unroll
            for (int r2 = 0; r2 < 2; ++r2) {
                int o = mbase + mi * 16 + g + r2 * 8;
                #pragma unroll
                for (int ni = 0; ni < 8; ++ni)
                    #pragma unroll
                    for (int c = 0; c < 2; ++c) {
                        int l = ni * 8 + tg * 2 + c;
                        SK[batch * SK_BSTRIDE + l * 132 + o] = d[mi][ni][r2 * 2 + c];
                    }
            }
    }
    __syncthreads();

    // ================ layernorms ================
    if (t < 16) {
        const int batch = t >> 3, h = t & 7;
        float qv[16];
        float m = 0.f;
        #pragma unroll
        for (int d = 0; d < 16; ++d) {
            qv[d] = Sq[batch * 128 + h * 16 + d] * (1.0f / 56.0f);
            m += qv[d];
        }
        m *= (1.0f / 16.0f);
        float var = 0.f;
        #pragma unroll
        for (int d = 0; d < 16; ++d) { float dd = qv[d] - m; var += dd * dd; }
        var *= (1.0f / 16.0f);
        float rs = rsqrtf(var + LN_EPS);
        #pragma unroll
        for (int d = 0; d < 16; ++d)
            Sqn[batch * 128 + h * 16 + d] = ((qv[d] - m) * rs * qn_w[d] + qn_b[d]) * SCALING;
    }
    for (int i = t; i < 896; i += 256) {
        const int batch = (i >= 448) ? 1 : 0;
        const int g2 = i - batch * 448;
        const int l = g2 >> 3, h = g2 & 7;
        float* kp = SK + batch * SK_BSTRIDE + l * 132 + h * 16;
        float m = 0.f;
        #pragma unroll
        for (int d = 0; d < 16; ++d) m += kp[d];
        m *= (1.0f / 16.0f);
        float var = 0.f;
        #pragma unroll
        for (int d = 0; d < 16; ++d) { float dd = kp[d] - m; var += dd * dd; }
        var *= (1.0f / 16.0f);
        float rs = rsqrtf(var + LN_EPS);
        #pragma unroll
        for (int d = 0; d < 16; ++d)
            kp[d] = (kp[d] - m) * rs * kn_w[d] + kn_b[d];
    }
    __syncthreads();

    // ================ attention + double softmax ================
    for (int i = t; i < 896; i += 256) {
        const int batch = (i >= 448) ? 1 : 0;
        const int g2 = i - batch * 448;
        const int l = g2 >> 3, h = g2 & 7;
        const float* qp = Sqn + batch * 128 + h * 16;
        const float* kp = SK + batch * SK_BSTRIDE + l * 132 + h * 16;
        float s = 0.f;
        #pragma unroll
        for (int d = 0; d < 16; ++d) s += qp[d] * kp[d];
        SA[batch * 480 + h * 60 + l] = s;
    }
    __syncthreads();
    if (t < 16) {
        const int batch = t >> 3, h = t & 7;
        float* row = SA + batch * 480 + h * 60;
        float mx = -1e30f;
        for (int l = 0; l < 56; ++l) mx = fmaxf(mx, row[l]);
        float sum = 0.f;
        for (int l = 0; l < 56; ++l) { float e = __expf(row[l] - mx); row[l] = e; sum += e; }
        float inv = 1.0f / sum;
        for (int l = 0; l < 56; ++l) row[l] *= inv;
    }
    __syncthreads();
    if (t < 8) {
        const int batch = t >> 2, hh = t & 3;
        const float lam = Ssc[0];
        const float* p0 = SA + batch * 480 + (2 * hh) * 60;
        const float* p1 = SA + batch * 480 + (2 * hh + 1) * 60;
        float* dst = SA2 + batch * 240 + hh * 60;
        float mx = -1e30f;
        for (int l = 0; l < 56; ++l) {
            float v = p0[l] - lam * p1[l];
            dst[l] = v;
            mx = fmaxf(mx, v);
        }
        float sum = 0.f;
        for (int l = 0; l < 56; ++l) { float e = __expf(dst[l] - mx); dst[l] = e; sum += e; }
        float inv = 1.0f / sum;
        for (int l = 0; l < 56; ++l) dst[l] *= inv;
    }
    __syncthreads();
    if (t < 112) {
        const int batch = (t >= 56) ? 1 : 0;
        const int l = t - batch * 56;
        const float* base = SA2 + batch * 240;
        out[((size_t)blockIdx.x * 2 + batch) * 56 + l] =
            0.25f * (base[l] + base[60 + l] + base[120 + l] + base[180 + l]);
    }
}

extern "C" void kernel_launch(void* const* d_in, const int* in_sizes, int n_in,
                              void* d_out, int out_size) {
    const float* x       = (const float*)d_in[0];
    const float* w_emb   = (const float*)d_in[1];
    const float* b_emb   = (const float*)d_in[2];
    const float* w_atlas = (const float*)d_in[3];
    const float* b_atlas = (const float*)d_in[4];
    const float* w_k     = (const float*)d_in[5];
    const float* qn_w    = (const float*)d_in[6];
    const float* qn_b    = (const float*)d_in[7];
    const float* kn_w    = (const float*)d_in[8];
    const float* kn_b    = (const float*)d_in[9];
    const float* lq1     = (const float*)d_in[10];
    const float* lk1     = (const float*)d_in[11];
    const float* lq2     = (const float*)d_in[12];
    const float* lk2     = (const float*)d_in[13];
    float* out = (float*)d_out;

    const int B = in_sizes[0] / (A_DIM * E_DIM);

    repack_kernel<<<(W_TOTAL + 255) / 256, 256>>>(w_emb, w_atlas, w_k);

    const size_t smem = SMEM_WORDS * sizeof(unsigned);
    cudaFuncSetAttribute(atlas_mdattn_tc,
                         cudaFuncAttributeMaxDynamicSharedMemorySize, (int)smem);
    atlas_mdattn_tc<<<B / 2, 256, smem>>>(
        x, b_emb, b_atlas,
        qn_w, qn_b, kn_w, kn_b, lq1, lk1, lq2, lk2, out);
}

// round 5
// speedup vs baseline: 3.0171x; 1.0056x over previous
#include <cuda_runtime.h>
#include <math.h>

// ---- problem constants ----
#define A_DIM 56
#define E_DIM 128
#define LAMBDA_INIT 0.7f
#define LN_EPS 1e-5f
#define SCALING 0.25f   // HD^-0.5, HD=16

// ---- repacked weight sizes (32-bit words) ----
#define W1_WORDS (2 * 49 * 256)    // conv1: 2 m-groups, K=392 (49 ksteps)
#define W2_WORDS (4 * 112 * 256)   // conv2: 4 m-groups, K=896 (112 ksteps)
#define W3_WORDS (4 * 16 * 256)    // kproj: 4 m-groups, K=128 (16 ksteps)
#define W_TOTAL  (W1_WORDS + W2_WORDS + W3_WORDS)

__device__ __align__(16) unsigned g_w1[W1_WORDS];
__device__ __align__(16) unsigned g_w2[W2_WORDS];
__device__ __align__(16) unsigned g_w3[W3_WORDS];

// ---- smem layout (32-bit words) ----
// SX: [2][64][136] tf32 x, halo-padded (col = 3+e), stride 136 ≡ 8 (mod 32)
#define SX_STRIDE  136
#define SX_BSTRIDE (64 * SX_STRIDE)
#define SZ_SX      (2 * SX_BSTRIDE)
// SH1: [2][128][72] tf32 h1^T (col = 3+a), stride 72 ≡ 8 (mod 32); reused as SK fp32 [2][64][132]
#define SH1_BSTRIDE (128 * 72)
#define SZ_SH1      (2 * SH1_BSTRIDE)
#define SK_BSTRIDE  (64 * 132)

#define OFF_SX   0
#define OFF_SH1  (OFF_SX + SZ_SX)
#define OFF_SQ   (OFF_SH1 + SZ_SH1)
#define OFF_SQN  (OFF_SQ + 256)
#define OFF_SA   (OFF_SQN + 256)
#define OFF_SA2  (OFF_SA + 960)
#define OFF_SC   (OFF_SA2 + 480)
#define SMEM_WORDS (OFF_SC + 4)

__device__ __forceinline__ unsigned f2tf(float f) {
    unsigned u;
    asm("cvt.rna.tf32.f32 %0, %1;" : "=r"(u) : "f"(f));
    return u;
}
__device__ __forceinline__ float silu_f(float v) {
    return v / (1.0f + __expf(-v));
}
__device__ __forceinline__ void mma_tf32(float* d, const unsigned* a, const unsigned* b) {
    asm volatile(
        "mma.sync.aligned.m16n8k8.row.col.f32.tf32.tf32.f32 "
        "{%0,%1,%2,%3}, {%4,%5,%6,%7}, {%8,%9}, {%0,%1,%2,%3};"
        : "+f"(d[0]), "+f"(d[1]), "+f"(d[2]), "+f"(d[3])
        : "r"(a[0]), "r"(a[1]), "r"(a[2]), "r"(a[3]), "r"(b[0]), "r"(b[1]));
}

// ================== weight repack: fragment-order tf32, TAP-MAJOR k ==================
// Fragment layout per m-group block: word idx = ks*256 + j2*64 + lane*2 + p,
// j = 2*j2+p, mi = j>>2, r = j&3,
// row = mg*32 + mi*16 + g + (r&1)*8, k' = ks*8 + tg + (r>=2)*4.
// Tap-major k-order: conv1: k' = dk*56 + ia  -> src col = ia*7 + dk
//                    conv2: k' = dk*128 + ie -> src col = ie*7 + dk
//                    kproj: k' = e (unchanged)
__global__ void __launch_bounds__(256)
repack_kernel(const float* __restrict__ w_emb,
              const float* __restrict__ w_atlas,
              const float* __restrict__ w_k)
{
    int i = blockIdx.x * 256 + threadIdx.x;
    if (i >= W_TOTAL) return;

    const float* src;
    unsigned* dst;
    int K, src_stride, row_lim, ii, which;
    if (i < W1_WORDS) {
        ii = i; src = w_emb; dst = g_w1; K = 49; src_stride = 392; row_lim = 56; which = 1;
    } else if (i < W1_WORDS + W2_WORDS) {
        ii = i - W1_WORDS; src = w_atlas; dst = g_w2; K = 112; src_stride = 896; row_lim = 128; which = 2;
    } else {
        ii = i - W1_WORDS - W2_WORDS; src = w_k; dst = g_w3; K = 16; src_stride = 128; row_lim = 128; which = 3;
    }
    int p    = ii & 1;
    int lane = (ii >> 1) & 31;
    int j2   = (ii >> 6) & 3;
    int blk  = ii >> 8;            // mg*K + ks
    int ks   = blk % K;
    int mg   = blk / K;
    int j    = j2 * 2 + p;
    int mi   = j >> 2, r = j & 3;
    int g = lane >> 2, tg = lane & 3;
    int row = mg * 32 + mi * 16 + g + ((r & 1) ? 8 : 0);
    int kk  = ks * 8 + tg + ((r >= 2) ? 4 : 0);
    int col;
    if (which == 1)      col = (kk % 56) * 7 + kk / 56;
    else if (which == 2) col = (kk % 128) * 7 + kk / 128;
    else                 col = kk;
    float v = (row < row_lim) ? src[row * src_stride + col] : 0.f;
    dst[ii] = f2tf(v);
}

extern __shared__ unsigned smw[];

__global__ void __launch_bounds__(256, 1)
atlas_mdattn_tc(
    const float* __restrict__ x,       // [B,56,128]
    const float* __restrict__ b_emb,   // [56]
    const float* __restrict__ b_atlas, // [128]
    const float* __restrict__ qn_w, const float* __restrict__ qn_b,
    const float* __restrict__ kn_w, const float* __restrict__ kn_b,
    const float* __restrict__ lq1, const float* __restrict__ lk1,
    const float* __restrict__ lq2, const float* __restrict__ lk2,
    float* __restrict__ out)           // [B,56]
{
    const int t = threadIdx.x;
    const int lane = t & 31, wid = t >> 5;
    const int g = lane >> 2, tg = lane & 3;

    unsigned* SX  = smw + OFF_SX;
    unsigned* SH1 = smw + OFF_SH1;
    float* Sq  = (float*)(smw + OFF_SQ);
    float* Sqn = (float*)(smw + OFF_SQN);
    float* SA  = (float*)(smw + OFF_SA);
    float* SA2 = (float*)(smw + OFF_SA2);
    float* Ssc = (float*)(smw + OFF_SC);
    float* SK  = (float*)SH1;

    // ---------------- init ----------------
    {
        uint4 z = make_uint4(0, 0, 0, 0);
        uint4* p = (uint4*)smw;
        for (int i = t; i < (SZ_SX + SZ_SH1) / 4; i += 256) p[i] = z;
    }
    if (t == 0) {
        float s1 = 0.f, s2 = 0.f;
        #pragma unroll
        for (int d = 0; d < 16; ++d) { s1 += lq1[d] * lk1[d]; s2 += lq2[d] * lk2[d]; }
        Ssc[0] = __expf(s1) - __expf(s2) + LAMBDA_INIT;
    }
    __syncthreads();

    // load x (2 batches), tf32, halo-padded
    const float* xb = x + (size_t)blockIdx.x * 2 * (A_DIM * E_DIM);
    #pragma unroll
    for (int bb = 0; bb < 2; ++bb) {
        for (int i = t; i < A_DIM * E_DIM; i += 256) {
            int l = i >> 7, e = i & 127;
            SX[bb * SX_BSTRIDE + l * SX_STRIDE + 3 + e] = f2tf(xb[bb * A_DIM * E_DIM + i]);
        }
    }
    __syncthreads();

    // ============ conv1: D[oa 64, (b,e) 256] = Wemb x im2col(x), K=392 tap-major ============
    // kstep ks: dk = ks/7 (constant in-step), ia = (ks%7)*8 + tg (+4 for second half)
    {
        const int mg = wid & 1, ng = wid >> 1;
        const int mbase = mg * 32;
        const int batch = ng >> 1;
        const int ebase = (ng * 64) & 127;
        const unsigned* SXb = SX + batch * SX_BSTRIDE;
        const uint2* Wp = (const uint2*)(g_w1 + mg * (49 * 256));

        float d[2][8][4];
        #pragma unroll
        for (int mi = 0; mi < 2; ++mi)
            #pragma unroll
            for (int ni = 0; ni < 8; ++ni)
                #pragma unroll
                for (int r = 0; r < 4; ++r) d[mi][ni][r] = 0.f;

        uint2 P[4][4];
        #pragma unroll
        for (int s = 0; s < 4; ++s)
            #pragma unroll
            for (int j2 = 0; j2 < 4; ++j2)
                P[s][j2] = Wp[s * 128 + j2 * 32 + lane];

        #pragma unroll 1
        for (int ks = 0; ks < 49; ++ks) {
            const int sb = ks & 3;
            unsigned a0[4] = { P[sb][0].x, P[sb][0].y, P[sb][1].x, P[sb][1].y };
            unsigned a1[4] = { P[sb][2].x, P[sb][2].y, P[sb][3].x, P[sb][3].y };
            if (ks + 4 < 49) {
                #pragma unroll
                for (int j2 = 0; j2 < 4; ++j2)
                    P[sb][j2] = Wp[(ks + 4) * 128 + j2 * 32 + lane];
            }
            const int dk = ks / 7;
            const int ia = (ks % 7) * 8 + tg;
            // x[ia][e+dk-3] at padded addr = ia*136 + (e+dk); e = ebase + g + ni*8
            const unsigned* B0 = SXb + ia * SX_STRIDE + ebase + g + dk;
            const unsigned* B1 = B0 + 4 * SX_STRIDE;
            #pragma unroll
            for (int ni = 0; ni < 8; ++ni) {
                unsigned b[2] = { B0[ni * 8], B1[ni * 8] };
                mma_tf32(d[0][ni], a0, b);
                mma_tf32(d[1][ni], a1, b);
            }
        }
        // epilogue: bias + SiLU, store transposed tf32 into SH1[batch][e][oa+3]
        #pragma unroll
        for (int mi = 0; mi < 2; ++mi)
            #pragma unroll
            for (int r2 = 0; r2 < 2; ++r2) {
                int oa = mbase + mi * 16 + g + r2 * 8;
                if (oa < 56) {
                    float bias = b_emb[oa];
                    #pragma unroll
                    for (int ni = 0; ni < 8; ++ni)
                        #pragma unroll
                        for (int c = 0; c < 2; ++c) {
                            int e = ebase + ni * 8 + tg * 2 + c;
                            float v = silu_f(d[mi][ni][r2 * 2 + c] + bias);
                            SH1[batch * SH1_BSTRIDE + e * 72 + oa + 3] = f2tf(v);
                        }
                }
            }
    }
    __syncthreads();

    // ============ conv2: D[oe 128, (b,a) 128] = Watlas x im2col(h1T), K=896 tap-major ============
    // kstep ks: dk = ks/16 (constant in-step), ie = (ks%16)*8 + tg (+4 second half)
    {
        const int mg = wid & 3, batch = wid >> 2;
        const int mbase = mg * 32;
        const unsigned* SHb = SH1 + batch * SH1_BSTRIDE;
        const uint2* Wp = (const uint2*)(g_w2 + mg * (112 * 256));

        float d[2][8][4];
        #pragma unroll
        for (int mi = 0; mi < 2; ++mi)
            #pragma unroll
            for (int ni = 0; ni < 8; ++ni)
                #pragma unroll
                for (int r = 0; r < 4; ++r) d[mi][ni][r] = 0.f;

        uint2 P[4][4];
        #pragma unroll
        for (int s = 0; s < 4; ++s)
            #pragma unroll
            for (int j2 = 0; j2 < 4; ++j2)
                P[s][j2] = Wp[s * 128 + j2 * 32 + lane];

        #pragma unroll 1
        for (int ks = 0; ks < 112; ++ks) {
            const int sb = ks & 3;
            unsigned a0[4] = { P[sb][0].x, P[sb][0].y, P[sb][1].x, P[sb][1].y };
            unsigned a1[4] = { P[sb][2].x, P[sb][2].y, P[sb][3].x, P[sb][3].y };
            if (ks + 4 < 112) {
                #pragma unroll
                for (int j2 = 0; j2 < 4; ++j2)
                    P[sb][j2] = Wp[(ks + 4) * 128 + j2 * 32 + lane];
            }
            const int dk = ks >> 4;
            const int ie = (ks & 15) * 8 + tg;
            // h1T[ie][a+dk-3] at padded addr = ie*72 + (a+dk); a = g + ni*8
            const unsigned* B0 = SHb + ie * 72 + g + dk;
            const unsigned* B1 = B0 + 4 * 72;
            #pragma unroll
            for (int ni = 0; ni < 8; ++ni) {
                unsigned b[2] = { B0[ni * 8], B1[ni * 8] };
                mma_tf32(d[0][ni], a0, b);
                mma_tf32(d[1][ni], a1, b);
            }
        }
        // epilogue: bias + SiLU + masked sum over a + quad reduce -> Sq
        #pragma unroll
        for (int mi = 0; mi < 2; ++mi)
            #pragma unroll
            for (int r2 = 0; r2 < 2; ++r2) {
                int oe = mbase + mi * 16 + g + r2 * 8;
                float bias = b_atlas[oe];
                float s = 0.f;
                #pragma unroll
                for (int ni = 0; ni < 7; ++ni) {
                    s += silu_f(d[mi][ni][r2 * 2 + 0] + bias);
                    s += silu_f(d[mi][ni][r2 * 2 + 1] + bias);
                }
                s += __shfl_xor_sync(0xffffffffu, s, 1);
                s += __shfl_xor_sync(0xffffffffu, s, 2);
                if (tg == 0) Sq[batch * 128 + oe] = s;
            }
    }
    __syncthreads();

    // ============ k-proj: D[o 128, (b,l) 128] = Wk x x^T, K=128 ============
    {
        const int mg = wid & 3, batch = wid >> 2;
        const int mbase = mg * 32;
        const unsigned* SXb = SX + batch * SX_BSTRIDE;
        const uint2* Wp = (const uint2*)(g_w3 + mg * (16 * 256));

        float d[2][8][4];
        #pragma unroll
        for (int mi = 0; mi < 2; ++mi)
            #pragma unroll
            for (int ni = 0; ni < 8; ++ni)
                #pragma unroll
                for (int r = 0; r < 4; ++r) d[mi][ni][r] = 0.f;

        uint2 P[4][4];
        #pragma unroll
        for (int s = 0; s < 4; ++s)
            #pragma unroll
            for (int j2 = 0; j2 < 4; ++j2)
                P[s][j2] = Wp[s * 128 + j2 * 32 + lane];

        #pragma unroll 1
        for (int ks = 0; ks < 16; ++ks) {
            const int sb = ks & 3;
            unsigned a0[4] = { P[sb][0].x, P[sb][0].y, P[sb][1].x, P[sb][1].y };
            unsigned a1[4] = { P[sb][2].x, P[sb][2].y, P[sb][3].x, P[sb][3].y };
            if (ks + 4 < 16) {
                #pragma unroll
                for (int j2 = 0; j2 < 4; ++j2)
                    P[sb][j2] = Wp[(ks + 4) * 128 + j2 * 32 + lane];
            }
            const unsigned* Bp = SXb + g * SX_STRIDE + 3 + ks * 8 + tg;
            #pragma unroll
            for (int ni = 0; ni < 8; ++ni) {
                unsigned b[2] = { Bp[ni * 8 * SX_STRIDE], Bp[ni * 8 * SX_STRIDE + 4] };
                mma_tf32(d[0][ni], a0, b);
                mma_tf32(d[1][ni], a1, b);
            }
        }
        __syncthreads();   // conv2 reads of SH1 done; safe to overwrite as SK
        #pragma unroll
        for (int mi = 0; mi < 2; ++mi)
            #pragma unroll
            for (int r2 = 0; r2 < 2; ++r2) {
                int o = mbase + mi * 16 + g + r2 * 8;
                #pragma unroll
                for (int ni = 0; ni < 8; ++ni)
                    #pragma unroll
                    for (int c = 0; c < 2; ++c) {
                        int l = ni * 8 + tg * 2 + c;
                        SK[batch * SK_BSTRIDE + l * 132 + o] = d[mi][ni][r2 * 2 + c];
                    }
            }
    }
    __syncthreads();

    // ================ layernorms ================
    if (t < 16) {
        const int batch = t >> 3, h = t & 7;
        float qv[16];
        float m = 0.f;
        #pragma unroll
        for (int d = 0; d < 16; ++d) {
            qv[d] = Sq[batch * 128 + h * 16 + d] * (1.0f / 56.0f);
            m += qv[d];
        }
        m *= (1.0f / 16.0f);
        float var = 0.f;
        #pragma unroll
        for (int d = 0; d < 16; ++d) { float dd = qv[d] - m; var += dd * dd; }
        var *= (1.0f / 16.0f);
        float rs = rsqrtf(var + LN_EPS);
        #pragma unroll
        for (int d = 0; d < 16; ++d)
            Sqn[batch * 128 + h * 16 + d] = ((qv[d] - m) * rs * qn_w[d] + qn_b[d]) * SCALING;
    }
    for (int i = t; i < 896; i += 256) {
        const int batch = (i >= 448) ? 1 : 0;
        const int g2 = i - batch * 448;
        const int l = g2 >> 3, h = g2 & 7;
        float* kp = SK + batch * SK_BSTRIDE + l * 132 + h * 16;
        float m = 0.f;
        #pragma unroll
        for (int d = 0; d < 16; ++d) m += kp[d];
        m *= (1.0f / 16.0f);
        float var = 0.f;
        #pragma unroll
        for (int d = 0; d < 16; ++d) { float dd = kp[d] - m; var += dd * dd; }
        var *= (1.0f / 16.0f);
        float rs = rsqrtf(var + LN_EPS);
        #pragma unroll
        for (int d = 0; d < 16; ++d)
            kp[d] = (kp[d] - m) * rs * kn_w[d] + kn_b[d];
    }
    __syncthreads();

    // ================ attention + double softmax ================
    for (int i = t; i < 896; i += 256) {
        const int batch = (i >= 448) ? 1 : 0;
        const int g2 = i - batch * 448;
        const int l = g2 >> 3, h = g2 & 7;
        const float* qp = Sqn + batch * 128 + h * 16;
        const float* kp = SK + batch * SK_BSTRIDE + l * 132 + h * 16;
        float s = 0.f;
        #pragma unroll
        for (int d = 0; d < 16; ++d) s += qp[d] * kp[d];
        SA[batch * 480 + h * 60 + l] = s;
    }
    __syncthreads();
    if (t < 16) {
        const int batch = t >> 3, h = t & 7;
        float* row = SA + batch * 480 + h * 60;
        float mx = -1e30f;
        for (int l = 0; l < 56; ++l) mx = fmaxf(mx, row[l]);
        float sum = 0.f;
        for (int l = 0; l < 56; ++l) { float e = __expf(row[l] - mx); row[l] = e; sum += e; }
        float inv = 1.0f / sum;
        for (int l = 0; l < 56; ++l) row[l] *= inv;
    }
    __syncthreads();
    if (t < 8) {
        const int batch = t >> 2, hh = t & 3;
        const float lam = Ssc[0];
        const float* p0 = SA + batch * 480 + (2 * hh) * 60;
        const float* p1 = SA + batch * 480 + (2 * hh + 1) * 60;
        float* dst = SA2 + batch * 240 + hh * 60;
        float mx = -1e30f;
        for (int l = 0; l < 56; ++l) {
            float v = p0[l] - lam * p1[l];
            dst[l] = v;
            mx = fmaxf(mx, v);
        }
        float sum = 0.f;
        for (int l = 0; l < 56; ++l) { float e = __expf(dst[l] - mx); dst[l] = e; sum += e; }
        float inv = 1.0f / sum;
        for (int l = 0; l < 56; ++l) dst[l] *= inv;
    }
    __syncthreads();
    if (t < 112) {
        const int batch = (t >= 56) ? 1 : 0;
        const int l = t - batch * 56;
        const float* base = SA2 + batch * 240;
        out[((size_t)blockIdx.x * 2 + batch) * 56 + l] =
            0.25f * (base[l] + base[60 + l] + base[120 + l] + base[180 + l]);
    }
}

extern "C" void kernel_launch(void* const* d_in, const int* in_sizes, int n_in,
                              void* d_out, int out_size) {
    const float* x       = (const float*)d_in[0];
    const float* w_emb   = (const float*)d_in[1];
    const float* b_emb   = (const float*)d_in[2];
    const float* w_atlas = (const float*)d_in[3];
    const float* b_atlas = (const float*)d_in[4];
    const float* w_k     = (const float*)d_in[5];
    const float* qn_w    = (const float*)d_in[6];
    const float* qn_b    = (const float*)d_in[7];
    const float* kn_w    = (const float*)d_in[8];
    const float* kn_b    = (const float*)d_in[9];
    const float* lq1     = (const float*)d_in[10];
    const float* lk1     = (const float*)d_in[11];
    const float* lq2     = (const float*)d_in[12];
    const float* lk2     = (const float*)d_in[13];
    float* out = (float*)d_out;

    const int B = in_sizes[0] / (A_DIM * E_DIM);

    repack_kernel<<<(W_TOTAL + 255) / 256, 256>>>(w_emb, w_atlas, w_k);

    const size_t smem = SMEM_WORDS * sizeof(unsigned);
    cudaFuncSetAttribute(atlas_mdattn_tc,
                         cudaFuncAttributeMaxDynamicSharedMemorySize, (int)smem);
    atlas_mdattn_tc<<<B / 2, 256, smem>>>(
        x, b_emb, b_atlas,
        qn_w, qn_b, kn_w, kn_b, lq1, lk1, lq2, lk2, out);
}